// round 1
// baseline (speedup 1.0000x reference)
#include <cuda_runtime.h>
#include <math.h>

// out[i][c] = posenc(X[i]) . W[3*voxel_ids[i] + c],  c in {0,1,2}
// posenc channel map: enc[0..2] = x[0..2]; enc[3 + f*6 + s*3 + d] = sin/cos(x[d] * 2^f)
//   (s=0 -> sin, s=1 -> cos), f in [0,10), d in [0,3)
//
// One warp per point. Lane L handles enc channels k = L and k = L + 32 (k < 63).
// W row block for voxel v is 189 contiguous floats at W + 189*v, so per-channel
// loads W[189v + 63c + k] are coalesced across lanes.

#define WARPS_PER_BLOCK 8
#define THREADS_PER_BLOCK (WARPS_PER_BLOCK * 32)

__global__ void __launch_bounds__(THREADS_PER_BLOCK)
voxel_linear_kernel(const float* __restrict__ X,
                    const float* __restrict__ W,
                    const int* __restrict__ row_ids,
                    const int* __restrict__ voxel_ids,
                    float* __restrict__ out,
                    int n)
{
    const int warp = threadIdx.x >> 5;
    const int lane = threadIdx.x & 31;
    const int p = blockIdx.x * WARPS_PER_BLOCK + warp;
    if (p >= n) return;

    // Broadcast loads (same address across warp -> 1 sector, L1-cached)
    const float x0 = X[3 * p + 0];
    const float x1 = X[3 * p + 1];
    const float x2 = X[3 * p + 2];

    const int v = voxel_ids[p];
    const float* __restrict__ w = W + (size_t)189 * (size_t)v;

    float acc0 = 0.0f, acc1 = 0.0f, acc2 = 0.0f;

#pragma unroll
    for (int t = 0; t < 2; ++t) {
        const int k = lane + 32 * t;
        if (k < 63) {
            float e;
            if (k < 3) {
                e = (k == 0) ? x0 : ((k == 1) ? x1 : x2);
            } else {
                const int j = k - 3;
                const int f = j / 6;          // frequency index 0..9
                const int r = j - 6 * f;      // 0..5
                const int d = (r >= 3) ? (r - 3) : r;  // dim 0..2
                const float xv = (d == 0) ? x0 : ((d == 1) ? x1 : x2);
                const float ang = xv * (float)(1 << f);
                float s, c;
                sincosf(ang, &s, &c);         // accurate path; no sin/cos divergence
                e = (r < 3) ? s : c;
            }
            // Coalesced W loads: consecutive k across lanes
            acc0 = fmaf(e, w[k], acc0);
            acc1 = fmaf(e, w[63 + k], acc1);
            acc2 = fmaf(e, w[126 + k], acc2);
        }
    }

    // Warp butterfly reduction (all lanes end with the sum)
#pragma unroll
    for (int off = 16; off > 0; off >>= 1) {
        acc0 += __shfl_xor_sync(0xffffffffu, acc0, off);
        acc1 += __shfl_xor_sync(0xffffffffu, acc1, off);
        acc2 += __shfl_xor_sync(0xffffffffu, acc2, off);
    }

    if (lane == 0) {
        const int r = row_ids[p];
        out[3 * r + 0] = acc0;
        out[3 * r + 1] = acc1;
        out[3 * r + 2] = acc2;
    }
}

extern "C" void kernel_launch(void* const* d_in, const int* in_sizes, int n_in,
                              void* d_out, int out_size)
{
    const float* X         = (const float*)d_in[0];
    const float* W         = (const float*)d_in[1];
    const int*   row_ids   = (const int*)d_in[2];
    const int*   voxel_ids = (const int*)d_in[3];
    float*       out       = (float*)d_out;

    const int n = in_sizes[0] / 3;  // N_POINTS
    const int blocks = (n + WARPS_PER_BLOCK - 1) / WARPS_PER_BLOCK;
    voxel_linear_kernel<<<blocks, THREADS_PER_BLOCK>>>(X, W, row_ids, voxel_ids, out, n);
}

// round 3
// speedup vs baseline: 2.4745x; 2.4745x over previous
#include <cuda_runtime.h>

// out[r][c] = posenc(X[r]) . W[3*voxel_ids[p] + c],  r = row_ids[p]
//
// Strategy: repack W into g_Wr[voxel][3][64] with a column permutation such
// that each angle a=(f,d) has its sin/cos weights adjacent (j=2a, 2a+1),
// raw-x weights at j=60..62, pad j=63. Then an 8-lane subgroup per point:
// lane L owns floats j in {32h+4L .. 32h+4L+3 : h=0,1} = 2 float4 per channel,
// i.e. angles {16h+2L, 16h+2L+1} -> 4 __sincosf per lane, each feeding BOTH
// its sin and cos channel. 4 points per warp, shfl reduction over 8 lanes.

#define NUM_VOXELS 512
#define TPB 256
#define NBLOCKS 1184

// [voxel][channel(3)][64 floats] as float4: 48 float4 per voxel
__device__ float4 g_Wr[NUM_VOXELS * 48];

__global__ void repack_kernel(const float* __restrict__ W)
{
    int idx = blockIdx.x * blockDim.x + threadIdx.x;   // over 512*192 floats
    if (idx >= NUM_VOXELS * 192) return;
    int v = idx / 192;
    int t = idx - v * 192;
    int c = t >> 6;          // 0..2
    int j = t & 63;          // 0..63
    float val = 0.0f;
    if (j < 60) {
        int a = j >> 1;      // angle index 0..29
        int s = j & 1;       // 0=sin, 1=cos
        int f = a / 3;
        int d = a - 3 * f;
        int col = 3 + 6 * f + 3 * s + d;   // posenc column
        val = W[(3 * v + c) * 63 + col];
    } else if (j < 63) {
        val = W[(3 * v + c) * 63 + (j - 60)];   // raw x channels
    }
    ((float*)g_Wr)[idx] = val;
}

__global__ void __launch_bounds__(TPB)
voxel_linear_kernel(const float* __restrict__ X,
                    const int* __restrict__ row_ids,
                    const int* __restrict__ voxel_ids,
                    float* __restrict__ out,
                    int n, int nchunks)
{
    const int lane = threadIdx.x & 31;
    const int warp = threadIdx.x >> 5;
    const int L    = lane & 7;    // lane within subgroup
    const int sg   = lane >> 3;   // subgroup (point) within warp

    // Hoisted per-thread slot constants. Slot s = 2h+q covers angle
    // a = 16h + 2L + q (lane 7, h=1 slots are overwritten by raw channels).
    float scl[4];
    int   dsel[4];
#pragma unroll
    for (int s = 0; s < 4; ++s) {
        int a = 16 * (s >> 1) + 2 * L + (s & 1);
        int f = a / 3;               // <= 10
        dsel[s] = a - 3 * f;
        scl[s] = (float)(1 << f);
    }

    for (int chunk = blockIdx.x; chunk < nchunks; chunk += NBLOCKS) {
        const int p = chunk * 32 + warp * 4 + sg;
        const bool active = (p < n);
        const int pp = active ? p : 0;

        const int r = row_ids[pp];
        const int v = voxel_ids[pp];

        const float4* __restrict__ wr = g_Wr + v * 48;

        // Issue all weight loads up front (latency hidden by sincos work).
        // Channel c, half h: float4 index c*16 + h*8 + L.
        const float4 q00 = wr[      L];        // c0 h0
        const float4 q01 = wr[ 8  + L];        // c0 h1
        const float4 q10 = wr[16 + L];         // c1 h0
        const float4 q11 = wr[24 + L];         // c1 h1
        const float4 q20 = wr[32 + L];         // c2 h0
        const float4 q21 = wr[40 + L];         // c2 h1

        const float x0 = X[3 * r + 0];
        const float x1 = X[3 * r + 1];
        const float x2 = X[3 * r + 2];

        float e[8];
#pragma unroll
        for (int s = 0; s < 4; ++s) {
            float xv = (dsel[s] == 0) ? x0 : ((dsel[s] == 1) ? x1 : x2);
            __sincosf(xv * scl[s], &e[2 * s], &e[2 * s + 1]);
        }
        if (L == 7) {       // h=1 of lane 7 = raw channels + pad
            e[4] = x0; e[5] = x1; e[6] = x2; e[7] = 0.0f;
        }

        float a0, a1, a2;
        a0 = e[0]*q00.x; a0 = fmaf(e[1],q00.y,a0); a0 = fmaf(e[2],q00.z,a0); a0 = fmaf(e[3],q00.w,a0);
        a0 = fmaf(e[4],q01.x,a0); a0 = fmaf(e[5],q01.y,a0); a0 = fmaf(e[6],q01.z,a0); a0 = fmaf(e[7],q01.w,a0);
        a1 = e[0]*q10.x; a1 = fmaf(e[1],q10.y,a1); a1 = fmaf(e[2],q10.z,a1); a1 = fmaf(e[3],q10.w,a1);
        a1 = fmaf(e[4],q11.x,a1); a1 = fmaf(e[5],q11.y,a1); a1 = fmaf(e[6],q11.z,a1); a1 = fmaf(e[7],q11.w,a1);
        a2 = e[0]*q20.x; a2 = fmaf(e[1],q20.y,a2); a2 = fmaf(e[2],q20.z,a2); a2 = fmaf(e[3],q20.w,a2);
        a2 = fmaf(e[4],q21.x,a2); a2 = fmaf(e[5],q21.y,a2); a2 = fmaf(e[6],q21.z,a2); a2 = fmaf(e[7],q21.w,a2);

        // Reduce within the 8-lane subgroup.
#pragma unroll
        for (int off = 4; off > 0; off >>= 1) {
            a0 += __shfl_down_sync(0xffffffffu, a0, off, 8);
            a1 += __shfl_down_sync(0xffffffffu, a1, off, 8);
            a2 += __shfl_down_sync(0xffffffffu, a2, off, 8);
        }

        if (L == 0 && active) {
            out[3 * r + 0] = a0;
            out[3 * r + 1] = a1;
            out[3 * r + 2] = a2;
        }
    }
}

extern "C" void kernel_launch(void* const* d_in, const int* in_sizes, int n_in,
                              void* d_out, int out_size)
{
    const float* X         = (const float*)d_in[0];
    const float* W         = (const float*)d_in[1];
    const int*   row_ids   = (const int*)d_in[2];
    const int*   voxel_ids = (const int*)d_in[3];
    float*       out       = (float*)d_out;

    const int n = in_sizes[0] / 3;   // N_POINTS
    const int nchunks = (n + 31) / 32;

    repack_kernel<<<(NUM_VOXELS * 192 + 255) / 256, 256>>>(W);
    voxel_linear_kernel<<<NBLOCKS, TPB>>>(X, row_ids, voxel_ids, out, n, nchunks);
}